// round 4
// baseline (speedup 1.0000x reference)
#include <cuda_runtime.h>
#include <cuda_bf16.h>
#include <stdint.h>

// out[r,o] = tanh(scale(r) * dot(enc_row(r), W[o,:]) + b[o])
//   r = b*128 + m (m = l*4+n, l<32) -> M=4096 ; enc phys row = b*2048 + m
//   K=256, N=256. (Spectral DCT/mask/IDCT collapses to mask*enc since the
//   band mask is independent of the DCT index.)
//
// Split-bf16 GEMM on classic mma.sync (HMMA m16n8k16, legal at compute_103):
//   x = hi + lo (both bf16); D = AhBh + AhBl + AlBh, fp32 accum (~1e-6 err).
// Per CTA: M=128 (one batch), N=64, K=256 resident in SMEM (4 bf16 arrays,
// 192KB, XOR-swizzled for conflict-free ldmatrix). 8 warps = 4(M) x 2(N),
// each warp 32x32 via 2x4 m16n8 tiles. Grid (32,4) = 128 CTAs = 1 wave.

#define THREADS 256
#define OFF_AH 0
#define OFF_AL 65536
#define OFF_BH 131072
#define OFF_BL 163840
#define DYN_SMEM 196608

static __device__ __forceinline__ uint32_t smem_u32(const void* p) {
    uint32_t a;
    asm("{ .reg .u64 t; cvta.to.shared.u64 t, %1; cvt.u32.u64 %0, t; }"
        : "=r"(a) : "l"(p));
    return a;
}

static __device__ __forceinline__ void split2(float x, float y,
                                              uint32_t& hi, uint32_t& lo) {
    __nv_bfloat16 hx = __float2bfloat16(x);
    __nv_bfloat16 hy = __float2bfloat16(y);
    float rx = x - __bfloat162float(hx);
    float ry = y - __bfloat162float(hy);
    __nv_bfloat162 H = __halves2bfloat162(hx, hy);
    __nv_bfloat162 L = __floats2bfloat162_rn(rx, ry);
    hi = *reinterpret_cast<uint32_t*>(&H);
    lo = *reinterpret_cast<uint32_t*>(&L);
}

static __device__ __forceinline__ void ldmx4(uint32_t& r0, uint32_t& r1,
                                             uint32_t& r2, uint32_t& r3,
                                             uint32_t addr) {
    asm volatile("ldmatrix.sync.aligned.m8n8.x4.shared.b16 {%0,%1,%2,%3}, [%4];"
                 : "=r"(r0), "=r"(r1), "=r"(r2), "=r"(r3) : "r"(addr));
}

static __device__ __forceinline__ void mma16816(float* c, const uint32_t* a,
                                                uint32_t b0, uint32_t b1) {
    asm volatile(
        "mma.sync.aligned.m16n8k16.row.col.f32.bf16.bf16.f32 "
        "{%0,%1,%2,%3},{%4,%5,%6,%7},{%8,%9},{%0,%1,%2,%3};"
        : "+f"(c[0]), "+f"(c[1]), "+f"(c[2]), "+f"(c[3])
        : "r"(a[0]), "r"(a[1]), "r"(a[2]), "r"(a[3]), "r"(b0), "r"(b1));
}

static __device__ __forceinline__ float tanh_fast(float x) {
    // tanh(x) = 1 - 2/(exp(2x)+1): EX2+RCP MUFU path, ~1e-6 rel err.
    float e = __expf(2.0f * x);
    return 1.0f - __fdividef(2.0f, e + 1.0f);
}

// swizzled byte offset within one bf16 tile array: rows of 512B (256 bf16),
// 16B chunks XOR'd with (row&7) -> conflict-free ldmatrix columns.
static __device__ __forceinline__ uint32_t sw_addr(int row, int c4) {
    return (uint32_t)(row * 512) + ((((c4 >> 1) ^ (row & 7)) & 31) << 4)
         + (c4 & 1) * 8;
}

__global__ __launch_bounds__(THREADS) void spectral_hmma_kernel(
    const float* __restrict__ enc,
    const float* __restrict__ W,
    const float* __restrict__ bias,
    float* __restrict__ out)
{
    extern __shared__ __align__(16) uint8_t dyn[];
    const uint32_t sbase = smem_u32(dyn);

    const int tid = threadIdx.x;
    const int wid = tid >> 5;
    const int lid = tid & 31;
    const int bx = blockIdx.x;   // batch (M tile), 0..31
    const int by = blockIdx.y;   // N tile, 0..3

    // ---- load + split A: 128 rows x 256 f32 -> Ah/Al bf16
    {
        const int row = tid >> 1;           // 0..127
        const int c4b = (tid & 1) * 32;     // float4 index base
        const float4* ev =
            (const float4*)enc + ((size_t)(bx * 2048 + row)) * 64 + c4b;
        #pragma unroll 8
        for (int i = 0; i < 32; ++i) {
            const int c4 = c4b + i;
            float4 v = ev[i];
            uint2 h, l;
            split2(v.x, v.y, h.x, l.x);
            split2(v.z, v.w, h.y, l.y);
            uint32_t sw = sw_addr(row, c4);
            *(uint2*)(dyn + OFF_AH + sw) = h;
            *(uint2*)(dyn + OFF_AL + sw) = l;
        }
    }
    // ---- load + split B: W rows by*64..+63
    {
        const int row = tid >> 2;           // 0..63
        const int c4b = (tid & 3) * 16;
        const float4* wv =
            (const float4*)W + ((size_t)(by * 64 + row)) * 64 + c4b;
        #pragma unroll 8
        for (int i = 0; i < 16; ++i) {
            const int c4 = c4b + i;
            float4 v = wv[i];
            uint2 h, l;
            split2(v.x, v.y, h.x, l.x);
            split2(v.z, v.w, h.y, l.y);
            uint32_t sw = sw_addr(row, c4);
            *(uint2*)(dyn + OFF_BH + sw) = h;
            *(uint2*)(dyn + OFF_BL + sw) = l;
        }
    }
    __syncthreads();

    // ---- warp tiling: wm in 0..3 (M 32-rows), wn in 0..1 (N 32-cols)
    const int wm = wid & 3;
    const int wn = wid >> 2;
    const int rl = lid & 15;     // ldmatrix row-within-16
    const int kadd = lid >> 4;   // ldmatrix k-chunk half

    uint32_t aRowOff[2], bRowOff[2];
    int axor[2], bxor[2];
    #pragma unroll
    for (int t = 0; t < 2; ++t) {
        int ra = wm * 32 + t * 16 + rl;
        int rb = wn * 32 + t * 16 + rl;
        aRowOff[t] = ra * 512; axor[t] = ra & 7;
        bRowOff[t] = rb * 512; bxor[t] = rb & 7;
    }

    float acc[2][4][4];
    #pragma unroll
    for (int i = 0; i < 2; ++i)
        #pragma unroll
        for (int j = 0; j < 4; ++j)
            #pragma unroll
            for (int q = 0; q < 4; ++q)
                acc[i][j][q] = 0.f;

    const uint32_t aPass[3] = {sbase + OFF_AH, sbase + OFF_AH, sbase + OFF_AL};
    const uint32_t bPass[3] = {sbase + OFF_BH, sbase + OFF_BL, sbase + OFF_BH};

    #pragma unroll
    for (int p = 0; p < 3; ++p) {
        const uint32_t Ab = aPass[p], Bb = bPass[p];
        #pragma unroll
        for (int k16 = 0; k16 < 16; ++k16) {
            const int ch = k16 * 2 + kadd;
            uint32_t a[2][4];
            #pragma unroll
            for (int mt = 0; mt < 2; ++mt)
                ldmx4(a[mt][0], a[mt][1], a[mt][2], a[mt][3],
                      Ab + aRowOff[mt] + (((ch ^ axor[mt]) & 31) << 4));
            #pragma unroll
            for (int nt2 = 0; nt2 < 2; ++nt2) {
                uint32_t b0, b1, b2, b3;
                ldmx4(b0, b1, b2, b3,
                      Bb + bRowOff[nt2] + (((ch ^ bxor[nt2]) & 31) << 4));
                // b0: n0-7/k0-7, b1: n8-15/k0-7, b2: n0-7/k8-15, b3: n8-15/k8-15
                #pragma unroll
                for (int mt = 0; mt < 2; ++mt) {
                    mma16816(acc[mt][nt2 * 2 + 0], a[mt], b0, b2);
                    mma16816(acc[mt][nt2 * 2 + 1], a[mt], b1, b3);
                }
            }
        }
    }

    // ---- epilogue: band scale, bias, tanh, store
    const int qr = lid >> 2;
    const int qc = (lid & 3) * 2;
    #pragma unroll
    for (int mt = 0; mt < 2; ++mt) {
        #pragma unroll
        for (int h = 0; h < 2; ++h) {
            const int m = wm * 32 + mt * 16 + qr + h * 8;   // 0..127
            const int n = m & 3, ls = m >> 2;
            const float scale = (n == 0) ? 1.0f
                              : (n == 1) ? ((ls < 16) ? 0.1f : 1.0f)
                              : 0.1f;
            float* orow = out + ((size_t)(bx * 128 + m)) * 256
                              + by * 64 + wn * 32 + qc;
            const float* brow = bias + by * 64 + wn * 32 + qc;
            #pragma unroll
            for (int nt = 0; nt < 4; ++nt) {
                float2 bb = *(const float2*)(brow + nt * 8);
                float2 o;
                o.x = tanh_fast(fmaf(scale, acc[mt][nt][h * 2 + 0], bb.x));
                o.y = tanh_fast(fmaf(scale, acc[mt][nt][h * 2 + 1], bb.y));
                *(float2*)(orow + nt * 8) = o;
            }
        }
    }
}

extern "C" void kernel_launch(void* const* d_in, const int* in_sizes, int n_in,
                              void* d_out, int out_size) {
    const float* enc  = (const float*)d_in[0];
    const float* W    = (const float*)d_in[1];
    const float* bias = (const float*)d_in[2];
    float* out = (float*)d_out;

    cudaFuncSetAttribute(spectral_hmma_kernel,
                         cudaFuncAttributeMaxDynamicSharedMemorySize, DYN_SMEM);
    dim3 grid(32, 4);
    spectral_hmma_kernel<<<grid, THREADS, DYN_SMEM>>>(enc, W, bias, out);
}

// round 5
// speedup vs baseline: 1.6411x; 1.6411x over previous
#include <cuda_runtime.h>
#include <cuda_bf16.h>
#include <stdint.h>

// out[r,o] = tanh(scale(r) * dot(enc_row(r), W[o,:]) + b[o])
//   r = b*128 + m (m = l*4+n, l<32) -> M=4096 ; enc phys row = b*2048 + m
//   K=256, N=256. (Spectral DCT/mask/IDCT collapses to mask*enc since the
//   band mask is independent of the DCT index.)
//
// Split-bf16 GEMM on mma.sync m16n8k16 (legal at compute_103):
//   x = hi + lo (both bf16); D = AhBh + AhBl + AlBh, fp32 accum (~5e-6 err).
// Per CTA: M=128 (one batch), N=64, K=256 resident in SMEM (4 bf16 arrays,
// 192KB, XOR-swizzled for conflict-free ldmatrix). 8 warps = 4(M) x 2(N).
// FUSED single k16 loop: 8 ldmatrix.x4 + 24 HMMA per step, unroll 4
// (round-4's 3-pass full unroll hit 255 regs -> spills -> 31 us).

#define THREADS 256
#define OFF_AH 0
#define OFF_AL 65536
#define OFF_BH 131072
#define OFF_BL 163840
#define DYN_SMEM 196608

static __device__ __forceinline__ uint32_t smem_u32(const void* p) {
    uint32_t a;
    asm("{ .reg .u64 t; cvta.to.shared.u64 t, %1; cvt.u32.u64 %0, t; }"
        : "=r"(a) : "l"(p));
    return a;
}

static __device__ __forceinline__ void split2(float x, float y,
                                              uint32_t& hi, uint32_t& lo) {
    __nv_bfloat16 hx = __float2bfloat16(x);
    __nv_bfloat16 hy = __float2bfloat16(y);
    float rx = x - __bfloat162float(hx);
    float ry = y - __bfloat162float(hy);
    __nv_bfloat162 H = __halves2bfloat162(hx, hy);
    __nv_bfloat162 L = __floats2bfloat162_rn(rx, ry);
    hi = *reinterpret_cast<uint32_t*>(&H);
    lo = *reinterpret_cast<uint32_t*>(&L);
}

static __device__ __forceinline__ void ldmx4(uint32_t* r, uint32_t addr) {
    asm volatile("ldmatrix.sync.aligned.m8n8.x4.shared.b16 {%0,%1,%2,%3}, [%4];"
                 : "=r"(r[0]), "=r"(r[1]), "=r"(r[2]), "=r"(r[3]) : "r"(addr));
}

static __device__ __forceinline__ void mma16816(float* c, const uint32_t* a,
                                                uint32_t b0, uint32_t b1) {
    asm volatile(
        "mma.sync.aligned.m16n8k16.row.col.f32.bf16.bf16.f32 "
        "{%0,%1,%2,%3},{%4,%5,%6,%7},{%8,%9},{%0,%1,%2,%3};"
        : "+f"(c[0]), "+f"(c[1]), "+f"(c[2]), "+f"(c[3])
        : "r"(a[0]), "r"(a[1]), "r"(a[2]), "r"(a[3]), "r"(b0), "r"(b1));
}

static __device__ __forceinline__ float tanh_fast(float x) {
    float e = __expf(2.0f * x);
    return 1.0f - __fdividef(2.0f, e + 1.0f);
}

// swizzled byte offset: rows of 512B (256 bf16), 16B chunks XOR'd with row&7
static __device__ __forceinline__ uint32_t sw_addr(int row, int c4) {
    return (uint32_t)(row * 512) + ((((c4 >> 1) ^ (row & 7)) & 31) << 4)
         + (c4 & 1) * 8;
}

__global__ __launch_bounds__(THREADS, 1) void spectral_hmma_kernel(
    const float* __restrict__ enc,
    const float* __restrict__ W,
    const float* __restrict__ bias,
    float* __restrict__ out)
{
    extern __shared__ __align__(16) uint8_t dyn[];
    const uint32_t sbase = smem_u32(dyn);

    const int tid = threadIdx.x;
    const int wid = tid >> 5;
    const int lid = tid & 31;
    const int bx = blockIdx.x;   // batch (M tile), 0..31
    const int by = blockIdx.y;   // N tile, 0..3

    // ---- load + split A: 128 rows x 256 f32 -> Ah/Al bf16
    {
        const int row = tid >> 1;
        const int c4b = (tid & 1) * 32;
        const float4* ev =
            (const float4*)enc + ((size_t)(bx * 2048 + row)) * 64 + c4b;
        #pragma unroll 8
        for (int i = 0; i < 32; ++i) {
            const int c4 = c4b + i;
            float4 v = ev[i];
            uint2 h, l;
            split2(v.x, v.y, h.x, l.x);
            split2(v.z, v.w, h.y, l.y);
            uint32_t sw = sw_addr(row, c4);
            *(uint2*)(dyn + OFF_AH + sw) = h;
            *(uint2*)(dyn + OFF_AL + sw) = l;
        }
    }
    // ---- load + split B: W rows by*64..+63
    {
        const int row = tid >> 2;
        const int c4b = (tid & 3) * 16;
        const float4* wv =
            (const float4*)W + ((size_t)(by * 64 + row)) * 64 + c4b;
        #pragma unroll 8
        for (int i = 0; i < 16; ++i) {
            const int c4 = c4b + i;
            float4 v = wv[i];
            uint2 h, l;
            split2(v.x, v.y, h.x, l.x);
            split2(v.z, v.w, h.y, l.y);
            uint32_t sw = sw_addr(row, c4);
            *(uint2*)(dyn + OFF_BH + sw) = h;
            *(uint2*)(dyn + OFF_BL + sw) = l;
        }
    }
    __syncthreads();

    // ---- warp tiling: wm 0..3 (M 32-rows), wn 0..1 (N 32-cols)
    const int wm = wid & 3;
    const int wn = wid >> 2;
    const int rl = lid & 15;
    const int kadd = lid >> 4;

    uint32_t aRowOff[2], bRowOff[2];
    int axor[2], bxor[2];
    #pragma unroll
    for (int t = 0; t < 2; ++t) {
        int ra = wm * 32 + t * 16 + rl;
        int rb = wn * 32 + t * 16 + rl;
        aRowOff[t] = ra * 512; axor[t] = ra & 7;
        bRowOff[t] = rb * 512; bxor[t] = rb & 7;
    }

    float acc[2][4][4];
    #pragma unroll
    for (int i = 0; i < 2; ++i)
        #pragma unroll
        for (int j = 0; j < 4; ++j)
            #pragma unroll
            for (int q = 0; q < 4; ++q)
                acc[i][j][q] = 0.f;

    // ---- fused mainloop: 8 ldmatrix.x4 + 24 HMMA per k16
    #pragma unroll 4
    for (int k16 = 0; k16 < 16; ++k16) {
        const int ch = k16 * 2 + kadd;
        uint32_t aoff[2], boff[2];
        #pragma unroll
        for (int t = 0; t < 2; ++t) {
            aoff[t] = aRowOff[t] + (((ch ^ axor[t]) & 31) << 4);
            boff[t] = bRowOff[t] + (((ch ^ bxor[t]) & 31) << 4);
        }
        uint32_t ah[2][4], al[2][4], bh[2][4], bl[2][4];
        #pragma unroll
        for (int t = 0; t < 2; ++t) {
            ldmx4(ah[t], sbase + OFF_AH + aoff[t]);
            ldmx4(al[t], sbase + OFF_AL + aoff[t]);
            ldmx4(bh[t], sbase + OFF_BH + boff[t]);
            ldmx4(bl[t], sbase + OFF_BL + boff[t]);
        }
        #pragma unroll
        for (int mt = 0; mt < 2; ++mt) {
            #pragma unroll
            for (int nt = 0; nt < 2; ++nt) {
                float* c0 = acc[mt][nt * 2 + 0];
                float* c1 = acc[mt][nt * 2 + 1];
                mma16816(c0, ah[mt], bh[nt][0], bh[nt][2]);
                mma16816(c1, ah[mt], bh[nt][1], bh[nt][3]);
                mma16816(c0, ah[mt], bl[nt][0], bl[nt][2]);
                mma16816(c1, ah[mt], bl[nt][1], bl[nt][3]);
                mma16816(c0, al[mt], bh[nt][0], bh[nt][2]);
                mma16816(c1, al[mt], bh[nt][1], bh[nt][3]);
            }
        }
    }

    // ---- epilogue: band scale, bias, tanh, store
    const int qr = lid >> 2;
    const int qc = (lid & 3) * 2;
    #pragma unroll
    for (int mt = 0; mt < 2; ++mt) {
        #pragma unroll
        for (int h = 0; h < 2; ++h) {
            const int m = wm * 32 + mt * 16 + qr + h * 8;
            const int n = m & 3, ls = m >> 2;
            const float scale = (n == 0) ? 1.0f
                              : (n == 1) ? ((ls < 16) ? 0.1f : 1.0f)
                              : 0.1f;
            float* orow = out + ((size_t)(bx * 128 + m)) * 256
                              + by * 64 + wn * 32 + qc;
            const float* brow = bias + by * 64 + wn * 32 + qc;
            #pragma unroll
            for (int nt = 0; nt < 4; ++nt) {
                float2 bb = *(const float2*)(brow + nt * 8);
                float2 o;
                o.x = tanh_fast(fmaf(scale, acc[mt][nt][h * 2 + 0], bb.x));
                o.y = tanh_fast(fmaf(scale, acc[mt][nt][h * 2 + 1], bb.y));
                *(float2*)(orow + nt * 8) = o;
            }
        }
    }
}

extern "C" void kernel_launch(void* const* d_in, const int* in_sizes, int n_in,
                              void* d_out, int out_size) {
    const float* enc  = (const float*)d_in[0];
    const float* W    = (const float*)d_in[1];
    const float* bias = (const float*)d_in[2];
    float* out = (float*)d_out;

    cudaFuncSetAttribute(spectral_hmma_kernel,
                         cudaFuncAttributeMaxDynamicSharedMemorySize, DYN_SMEM);
    dim3 grid(32, 4);
    spectral_hmma_kernel<<<grid, THREADS, DYN_SMEM>>>(enc, W, bias, out);
}

// round 6
// speedup vs baseline: 2.4575x; 1.4975x over previous
#include <cuda_runtime.h>
#include <cuda_bf16.h>
#include <stdint.h>

// out[r,o] = tanh(scale(r) * dot(enc_row(r), W[o,:]) + b[o])
//   r = b*128 + m (m = l*4+n, l<32) -> M=4096 ; enc phys row = b*2048 + m
//   K=256, N=256. (Spectral DCT/mask/IDCT collapses to mask*enc since the
//   band mask is independent of the DCT index.)
//
// Split-bf16 GEMM on mma.sync m16n8k16 (legal at compute_103):
//   x = hi + lo (both bf16); D = AhBh + AhBl + AlBh, fp32 accum (~5e-6 err).
// Per CTA: M=128, N=64, K=256 resident in SMEM (4 bf16 arrays, 192KB,
// XOR-swizzled). 16 warps = 8(M) x 2(N), warp tile 16x32.
// Load phase: chunk-per-lane (one warp = one 512B smem row), STS.128,
// conflict-free. Grid (32,4) = 128 CTAs = 1 wave.

#define THREADS 512
#define OFF_AH 0
#define OFF_AL 65536
#define OFF_BH 131072
#define OFF_BL 163840
#define DYN_SMEM 196608

static __device__ __forceinline__ uint32_t smem_u32(const void* p) {
    uint32_t a;
    asm("{ .reg .u64 t; cvta.to.shared.u64 t, %1; cvt.u32.u64 %0, t; }"
        : "=r"(a) : "l"(p));
    return a;
}

static __device__ __forceinline__ void split2(float x, float y,
                                              uint32_t& hi, uint32_t& lo) {
    __nv_bfloat162 H = __floats2bfloat162_rn(x, y);
    float rx = x - __bfloat162float(H.x);
    float ry = y - __bfloat162float(H.y);
    __nv_bfloat162 L = __floats2bfloat162_rn(rx, ry);
    hi = *reinterpret_cast<uint32_t*>(&H);
    lo = *reinterpret_cast<uint32_t*>(&L);
}

static __device__ __forceinline__ void ldmx4(uint32_t* r, uint32_t addr) {
    asm volatile("ldmatrix.sync.aligned.m8n8.x4.shared.b16 {%0,%1,%2,%3}, [%4];"
                 : "=r"(r[0]), "=r"(r[1]), "=r"(r[2]), "=r"(r[3]) : "r"(addr));
}

static __device__ __forceinline__ void mma16816(float* c, const uint32_t* a,
                                                uint32_t b0, uint32_t b1) {
    asm volatile(
        "mma.sync.aligned.m16n8k16.row.col.f32.bf16.bf16.f32 "
        "{%0,%1,%2,%3},{%4,%5,%6,%7},{%8,%9},{%0,%1,%2,%3};"
        : "+f"(c[0]), "+f"(c[1]), "+f"(c[2]), "+f"(c[3])
        : "r"(a[0]), "r"(a[1]), "r"(a[2]), "r"(a[3]), "r"(b0), "r"(b1));
}

static __device__ __forceinline__ float tanh_fast(float x) {
    float e = __expf(2.0f * x);
    return 1.0f - __fdividef(2.0f, e + 1.0f);
}

__global__ __launch_bounds__(THREADS, 1) void spectral_hmma_kernel(
    const float* __restrict__ enc,
    const float* __restrict__ W,
    const float* __restrict__ bias,
    float* __restrict__ out)
{
    extern __shared__ __align__(16) uint8_t dyn[];
    const uint32_t sbase = smem_u32(dyn);

    const int tid = threadIdx.x;
    const int wid = tid >> 5;
    const int lid = tid & 31;
    const int bx = blockIdx.x;   // batch (M tile), 0..31
    const int by = blockIdx.y;   // N tile, 0..3

    // ---- load + split A: one warp covers one smem row (32 x 16B chunks)
    // per iter; coalesced 1KB LDG per warp; conflict-free STS.128.
    {
        #pragma unroll
        for (int it = 0; it < 8; ++it) {
            const int g   = tid + it * 512;      // chunk id, 0..4095
            const int row = g >> 5;              // 0..127
            const int ck  = g & 31;              // 16B chunk within row
            const float4* src =
                (const float4*)enc + ((size_t)(bx * 2048 + row)) * 64 + ck * 2;
            float4 v0 = src[0], v1 = src[1];
            uint4 h, l;
            split2(v0.x, v0.y, h.x, l.x);
            split2(v0.z, v0.w, h.y, l.y);
            split2(v1.x, v1.y, h.z, l.z);
            split2(v1.z, v1.w, h.w, l.w);
            uint32_t sw = row * 512 + (((ck ^ (row & 7)) & 31) << 4);
            *(uint4*)(dyn + OFF_AH + sw) = h;
            *(uint4*)(dyn + OFF_AL + sw) = l;
        }
    }
    // ---- load + split B: W rows by*64..+63
    {
        #pragma unroll
        for (int it = 0; it < 4; ++it) {
            const int g   = tid + it * 512;      // 0..2047
            const int row = g >> 5;              // 0..63
            const int ck  = g & 31;
            const float4* src =
                (const float4*)W + ((size_t)(by * 64 + row)) * 64 + ck * 2;
            float4 v0 = src[0], v1 = src[1];
            uint4 h, l;
            split2(v0.x, v0.y, h.x, l.x);
            split2(v0.z, v0.w, h.y, l.y);
            split2(v1.x, v1.y, h.z, l.z);
            split2(v1.z, v1.w, h.w, l.w);
            uint32_t sw = row * 512 + (((ck ^ (row & 7)) & 31) << 4);
            *(uint4*)(dyn + OFF_BH + sw) = h;
            *(uint4*)(dyn + OFF_BL + sw) = l;
        }
    }
    __syncthreads();

    // ---- warp tiling: 16 warps = 8(M, 16 rows) x 2(N, 32 cols)
    const int wm = wid & 7;
    const int wn = wid >> 3;
    const int rl = lid & 15;
    const int kadd = lid >> 4;

    const int aRow = wm * 16 + rl;
    const uint32_t aRowOff = aRow * 512;
    const int axor = aRow & 7;
    uint32_t bRowOff[2];
    int bxor[2];
    #pragma unroll
    for (int t = 0; t < 2; ++t) {
        int rb = wn * 32 + t * 16 + rl;
        bRowOff[t] = rb * 512;
        bxor[t] = rb & 7;
    }

    float acc[4][4];
    #pragma unroll
    for (int j = 0; j < 4; ++j)
        #pragma unroll
        for (int q = 0; q < 4; ++q)
            acc[j][q] = 0.f;

    // ---- fused mainloop: 6 ldmatrix.x4 + 12 HMMA per k16
    #pragma unroll 4
    for (int k16 = 0; k16 < 16; ++k16) {
        const int ch = k16 * 2 + kadd;
        const uint32_t aoff = aRowOff + (((ch ^ axor) & 31) << 4);
        uint32_t ah[4], al[4], bh[2][4], bl[2][4];
        ldmx4(ah, sbase + OFF_AH + aoff);
        ldmx4(al, sbase + OFF_AL + aoff);
        #pragma unroll
        for (int t = 0; t < 2; ++t) {
            const uint32_t boff = bRowOff[t] + (((ch ^ bxor[t]) & 31) << 4);
            ldmx4(bh[t], sbase + OFF_BH + boff);
            ldmx4(bl[t], sbase + OFF_BL + boff);
        }
        #pragma unroll
        for (int t = 0; t < 2; ++t) {
            float* c0 = acc[t * 2 + 0];
            float* c1 = acc[t * 2 + 1];
            mma16816(c0, ah, bh[t][0], bh[t][2]);
            mma16816(c1, ah, bh[t][1], bh[t][3]);
            mma16816(c0, ah, bl[t][0], bl[t][2]);
            mma16816(c1, ah, bl[t][1], bl[t][3]);
            mma16816(c0, al, bh[t][0], bh[t][2]);
            mma16816(c1, al, bh[t][1], bh[t][3]);
        }
    }

    // ---- epilogue: band scale, bias, tanh, store
    const int qr = lid >> 2;
    const int qc = (lid & 3) * 2;
    #pragma unroll
    for (int h = 0; h < 2; ++h) {
        const int m = wm * 16 + qr + h * 8;      // 0..127
        const int n = m & 3, ls = m >> 2;
        const float scale = (n == 0) ? 1.0f
                          : (n == 1) ? ((ls < 16) ? 0.1f : 1.0f)
                          : 0.1f;
        float* orow = out + ((size_t)(bx * 128 + m)) * 256
                          + by * 64 + wn * 32 + qc;
        const float* brow = bias + by * 64 + wn * 32 + qc;
        #pragma unroll
        for (int nt = 0; nt < 4; ++nt) {
            float2 bb = *(const float2*)(brow + nt * 8);
            float2 o;
            o.x = tanh_fast(fmaf(scale, acc[nt][h * 2 + 0], bb.x));
            o.y = tanh_fast(fmaf(scale, acc[nt][h * 2 + 1], bb.y));
            *(float2*)(orow + nt * 8) = o;
        }
    }
}

extern "C" void kernel_launch(void* const* d_in, const int* in_sizes, int n_in,
                              void* d_out, int out_size) {
    const float* enc  = (const float*)d_in[0];
    const float* W    = (const float*)d_in[1];
    const float* bias = (const float*)d_in[2];
    float* out = (float*)d_out;

    cudaFuncSetAttribute(spectral_hmma_kernel,
                         cudaFuncAttributeMaxDynamicSharedMemorySize, DYN_SMEM);
    dim3 grid(32, 4);
    spectral_hmma_kernel<<<grid, THREADS, DYN_SMEM>>>(enc, W, bias, out);
}